// round 15
// baseline (speedup 1.0000x reference)
#include <cuda_runtime.h>
#include <cuda_bf16.h>
#include <math.h>
#include <stdint.h>

#define TT 512
#define BB 256
#define DIN 256
#define DLT 256
#define NCTA 128
#define NGRP 8          // CTAs per barrier group (one b-tile)

// output layout (floats): H[(T+1),B,DL], C[(T+1),B,DL], F[T,B,DL], I[T,B,DL], O[T,B,DL]
#define H_OFF 0
#define C_OFF ((TT + 1) * BB * DLT)
#define F_OFF (2 * (TT + 1) * BB * DLT)
#define I_OFF (F_OFF + TT * BB * DLT)
#define O_OFF (I_OFF + TT * BB * DLT)

// bf16 hi/lo scratch for X and x-side weights
__device__ __nv_bfloat16 g_Xhi[TT * BB * DIN];
__device__ __nv_bfloat16 g_Xlo[TT * BB * DIN];
__device__ __nv_bfloat16 g_Wxhi[4 * DLT * DIN];
__device__ __nv_bfloat16 g_Wxlo[4 * DLT * DIN];

// packed h, one buffer PER TIMESTEP. Depth 513 is load-bearing: with
// flags-only forward sync the intra-group skew bound is 1 step, so a fast CTA
// writes h_{t+2} while the slowest peer still reads h_t; any ring depth < 3
// (e.g. R10's parity-2) would collide without a full barrier.
__device__ __nv_bfloat16 g_Hpd[TT + 1][2][BB * DLT];

// per-producer data-ready flags: (group bt, producer jt), 128B separated.
// reset to 0 by convX block 0 each call (stream-ordered before persist).
__device__ unsigned int g_flagv[16 * 8 * 32];

// init-barrier state (cross-replay monotonic), 128B-separated
__device__ unsigned int g_cnt2[16 * 32];
__device__ unsigned int g_gen2[16 * 32];

__device__ __forceinline__ float sigm(float x) { return 1.0f / (1.0f + expf(-x)); }

__device__ __forceinline__ unsigned int ld_acquire_gpu(const unsigned int* p)
{
    unsigned int v;
    asm volatile("ld.acquire.gpu.global.u32 %0, [%1];" : "=r"(v) : "l"(p) : "memory");
    return v;
}
__device__ __forceinline__ void red_release_add(unsigned int* p, unsigned int v)
{
    asm volatile("red.release.gpu.global.add.u32 [%0], %1;" :: "l"(p), "r"(v) : "memory");
}
__device__ __forceinline__ void st_release_gpu(unsigned int* p, unsigned int v)
{
    asm volatile("st.release.gpu.global.u32 [%0], %1;" :: "l"(p), "r"(v) : "memory");
}
__device__ __forceinline__ void group_barrier(int slot, unsigned target)
{
    __syncthreads();
    if (threadIdx.x == 0) {
        __threadfence();
        if (atomicAdd(&g_cnt2[slot], 1) == NGRP - 1) {
            atomicExch(&g_cnt2[slot], 0);
            red_release_add(&g_gen2[slot], 1);
        } else {
            while (ld_acquire_gpu(&g_gen2[slot]) != target) { __nanosleep(32); }
        }
        __threadfence();
    }
    __syncthreads();
}

__device__ __forceinline__ void split2(float x, float y, uint32_t& hi, uint32_t& lo)
{
    __nv_bfloat16 hx = __float2bfloat16(x);
    __nv_bfloat16 hy = __float2bfloat16(y);
    __nv_bfloat16 lx = __float2bfloat16(x - __bfloat162float(hx));
    __nv_bfloat16 ly = __float2bfloat16(y - __bfloat162float(hy));
    __nv_bfloat162 h2 = __halves2bfloat162(hx, hy);
    __nv_bfloat162 l2 = __halves2bfloat162(lx, ly);
    hi = *(uint32_t*)&h2;
    lo = *(uint32_t*)&l2;
}

__device__ __forceinline__ void mma16816(float* d, const uint32_t* a, const uint32_t* b)
{
    asm volatile(
        "mma.sync.aligned.m16n8k16.row.col.f32.bf16.bf16.f32 "
        "{%0,%1,%2,%3}, {%4,%5,%6,%7}, {%8,%9}, {%0,%1,%2,%3};"
        : "+f"(d[0]), "+f"(d[1]), "+f"(d[2]), "+f"(d[3])
        : "r"(a[0]), "r"(a[1]), "r"(a[2]), "r"(a[3]), "r"(b[0]), "r"(b[1]));
}

__device__ __forceinline__ void ldsm4(uint32_t* r, uint32_t addr)
{
    asm volatile("ldmatrix.sync.aligned.m8n8.x4.shared.b16 {%0,%1,%2,%3}, [%4];"
                 : "=r"(r[0]), "=r"(r[1]), "=r"(r[2]), "=r"(r[3]) : "r"(addr));
}

__device__ __forceinline__ void cp16ca(uint32_t saddr, const void* g)
{
    asm volatile("cp.async.ca.shared.global [%0], [%1], 16;" :: "r"(saddr), "l"(g));
}
__device__ __forceinline__ void cp16cg(uint32_t saddr, const void* g)
{
    asm volatile("cp.async.cg.shared.global [%0], [%1], 16;" :: "r"(saddr), "l"(g));
}
__device__ __forceinline__ void cp_commit() { asm volatile("cp.async.commit_group;"); }
template<int N> __device__ __forceinline__ void cp_wait() { asm volatile("cp.async.wait_group %0;" :: "n"(N)); }

// ---------------------------------------------------------------------------
// converters (R10) + flag reset
// ---------------------------------------------------------------------------
__global__ void __launch_bounds__(256) convX_kernel(const float* __restrict__ X)
{
    if (blockIdx.x == 0 && threadIdx.x < 128) g_flagv[threadIdx.x * 32] = 0u;
    int idx = blockIdx.x * 256 + threadIdx.x;
    if (idx < TT * BB * DIN / 4) {
        float4 v = *(const float4*)&X[(size_t)idx * 4];
        uint32_t h01, l01, h23, l23;
        split2(v.x, v.y, h01, l01);
        split2(v.z, v.w, h23, l23);
        ((uint2*)g_Xhi)[idx] = make_uint2(h01, h23);
        ((uint2*)g_Xlo)[idx] = make_uint2(l01, l23);
    }
}

__global__ void __launch_bounds__(256) convW_kernel(
    const float* __restrict__ W0, const float* __restrict__ W1,
    const float* __restrict__ W2, const float* __restrict__ W3)
{
    int idx = blockIdx.x * 256 + threadIdx.x;
    int g = idx >> 14;
    int j = (idx >> 6) & 255;
    int q = idx & 63;
    const float* Wg = (g == 0) ? W0 : (g == 1) ? W1 : (g == 2) ? W2 : W3;
    float4 v = *(const float4*)&Wg[(size_t)j * 512 + 256 + q * 4];
    uint32_t h01, l01, h23, l23;
    split2(v.x, v.y, h01, l01);
    split2(v.z, v.w, h23, l23);
    int d2 = g * 16384 + j * 64 + q;
    ((uint2*)g_Wxhi)[d2] = make_uint2(h01, h23);
    ((uint2*)g_Wxlo)[d2] = make_uint2(l01, l23);
}

// ---------------------------------------------------------------------------
// phase 1 (R10, unchanged): cp.async double-buffered + ldmatrix.
// ---------------------------------------------------------------------------
#define P1S 40
#define CHUNK_B 10240
#define BUF_B   (4 * CHUNK_B)
#define P1SMEM  (2 * BUF_B)

__global__ void __launch_bounds__(256) phase1_kernel(
    const float* __restrict__ b0v, const float* __restrict__ b1v,
    const float* __restrict__ b2v, const float* __restrict__ b3v,
    float* __restrict__ out)
{
    extern __shared__ char smem[];
    const uint32_t shb = (uint32_t)__cvta_generic_to_shared(smem);

    const int p  = blockIdx.x;
    const int bx = p & 7;
    const int by = p >> 3;
    const int g  = bx >> 1;
    const int j0 = (bx & 1) * 128;
    const int m0 = by * 128;

    const float* bias = (g == 0) ? b0v : (g == 1) ? b1v : (g == 2) ? b2v : b3v;

    const int tid  = threadIdx.x;
    const int warp = tid >> 5;
    const int lane = tid & 31;
    const int wm = warp >> 1;
    const int wn = warp & 1;
    const int lg = lane >> 2;
    const int tq = lane & 3;
    const int rowsel = lane & 15;
    const int koff   = (lane >> 4) * 8;

    auto stage = [&](int c) {
        int c0 = c * 32;
        uint32_t bufb = shb + (c & 1) * BUF_B;
#pragma unroll
        for (int it = 0; it < 8; it++) {
            int sub  = it >> 1;
            int idx  = tid + (it & 1) * 256;
            int row  = idx >> 2;
            int q    = idx & 3;
            uint32_t sa = bufb + sub * CHUNK_B + (row * P1S + q * 8) * 2;
            const __nv_bfloat16* src;
            if (sub == 0)      src = &g_Xhi[(m0 + row) * 256 + c0 + q * 8];
            else if (sub == 1) src = &g_Xlo[(m0 + row) * 256 + c0 + q * 8];
            else if (sub == 2) src = &g_Wxhi[g * 65536 + (j0 + row) * 256 + c0 + q * 8];
            else               src = &g_Wxlo[g * 65536 + (j0 + row) * 256 + c0 + q * 8];
            cp16ca(sa, src);
        }
        cp_commit();
    };

    float acc[2][8][4];
#pragma unroll
    for (int i = 0; i < 2; i++)
#pragma unroll
        for (int j = 0; j < 8; j++)
#pragma unroll
            for (int u = 0; u < 4; u++) acc[i][j][u] = 0.0f;

    stage(0);

    for (int c = 0; c < 8; c++) {
        if (c + 1 < 8) { stage(c + 1); cp_wait<1>(); }
        else           { cp_wait<0>(); }
        __syncthreads();

        uint32_t bufb = shb + (c & 1) * BUF_B;
        uint32_t aoff = bufb + ((wm * 32 + rowsel) * P1S + koff) * 2;
        uint32_t boff = bufb + 2 * CHUNK_B + ((wn * 64 + rowsel) * P1S + koff) * 2;

#pragma unroll
        for (int kk = 0; kk < 32; kk += 16) {
            uint32_t ah[2][4], al[2][4];
#pragma unroll
            for (int i = 0; i < 2; i++) {
                ldsm4(ah[i], aoff + (i * 16 * P1S + kk) * 2);
                ldsm4(al[i], aoff + CHUNK_B + (i * 16 * P1S + kk) * 2);
            }
#pragma unroll
            for (int jj = 0; jj < 4; jj++) {
                uint32_t b4h[4], b4l[4];
                ldsm4(b4h, boff + (jj * 16 * P1S + kk) * 2);
                ldsm4(b4l, boff + CHUNK_B + (jj * 16 * P1S + kk) * 2);
                uint32_t bh0[2] = { b4h[0], b4h[2] };
                uint32_t bh1[2] = { b4h[1], b4h[3] };
                uint32_t bl0[2] = { b4l[0], b4l[2] };
                uint32_t bl1[2] = { b4l[1], b4l[3] };
#pragma unroll
                for (int i = 0; i < 2; i++) {
                    mma16816(acc[i][jj * 2 + 0], ah[i], bh0);
                    mma16816(acc[i][jj * 2 + 0], ah[i], bl0);
                    mma16816(acc[i][jj * 2 + 0], al[i], bh0);
                    mma16816(acc[i][jj * 2 + 1], ah[i], bh1);
                    mma16816(acc[i][jj * 2 + 1], ah[i], bl1);
                    mma16816(acc[i][jj * 2 + 1], al[i], bh1);
                }
            }
        }
        __syncthreads();
    }

#pragma unroll
    for (int i = 0; i < 2; i++) {
#pragma unroll
        for (int j = 0; j < 8; j++) {
            int col = j0 + wn * 64 + j * 8 + tq * 2;
            float bxv = bias[col], byv = bias[col + 1];
            int row0 = m0 + wm * 32 + i * 16 + lg;
#pragma unroll
            for (int h = 0; h < 2; h++) {
                int m = row0 + h * 8;
                float2 v;
                v.x = acc[i][j][h * 2 + 0] + bxv;
                v.y = acc[i][j][h * 2 + 1] + byv;
                int idx;
                if (g == 0)      idx = F_OFF + m * DLT + col;
                else if (g == 1) idx = I_OFF + m * DLT + col;
                else if (g == 2) idx = C_OFF + (m + BB) * DLT + col;
                else             idx = O_OFF + m * DLT + col;
                *(float2*)&out[idx] = v;
            }
        }
    }
}

// ---------------------------------------------------------------------------
// persist v6 (resubmit, audited): R10 + per-producer flag sync.
//  - depth-513 h buffer (no reuse -> no WAR, flags are forward-only)
//  - producer: publish h_{t+1} -> __syncthreads -> fence -> st.release flag
//  - consumer: warp w polls producer w's flag, stages that 32-col slice
// ---------------------------------------------------------------------------
#define PWS 264
#define WSH_B 0
#define WSL_B 67584
#define HS_B  135168
#define HL_REL 8448
#define SG_B  152064
#define CS_B  160768
#define PSMEM 162816

__global__ void __launch_bounds__(256) persist_kernel(
    const float* __restrict__ W0, const float* __restrict__ W1,
    const float* __restrict__ W2, const float* __restrict__ W3,
    float* __restrict__ out)
{
    extern __shared__ char smem[];
    __nv_bfloat16* wsH = (__nv_bfloat16*)(smem + WSH_B);
    __nv_bfloat16* wsL = (__nv_bfloat16*)(smem + WSL_B);
    float* sg = (float*)(smem + SG_B);
    float* cs = (float*)(smem + CS_B);
    const uint32_t shb = (uint32_t)__cvta_generic_to_shared(smem);

    const int tid = threadIdx.x;
    const int bt = blockIdx.x >> 3;
    const int jt = blockIdx.x & 7;
    const int b0 = bt * 16;
    const int j0 = jt * 32;
    const int slot = bt * 32;

    __shared__ unsigned s_gen0;
    if (tid == 0) s_gen0 = ld_acquire_gpu(&g_gen2[slot]);

#pragma unroll
    for (int it = 0; it < 32; it++) {
        int idx = tid + it * 256;
        int jc = idx >> 6;
        int kq = idx & 63;
        int gg = jc >> 5;
        int jr = j0 + (jc & 31);
        const float* Wg = (gg == 0) ? W0 : (gg == 1) ? W1 : (gg == 2) ? W2 : W3;
        float4 v = *(const float4*)&Wg[(size_t)jr * 512 + kq * 4];
        uint32_t h01, l01, h23, l23;
        split2(v.x, v.y, h01, l01);
        split2(v.z, v.w, h23, l23);
        int base = jc * PWS + kq * 4;
        *(uint32_t*)&wsH[base]     = h01;
        *(uint32_t*)&wsH[base + 2] = h23;
        *(uint32_t*)&wsL[base]     = l01;
        *(uint32_t*)&wsL[base + 2] = l23;
    }

    const int cell = tid * 2;
    const int ur  = cell >> 5;
    const int ujl = cell & 31;

    {
        float2 z = make_float2(0.0f, 0.0f);
        *(float2*)&cs[cell] = z;
        *(float2*)&out[H_OFF + (b0 + ur) * DLT + j0 + ujl] = z;
        *(float2*)&out[C_OFF + (b0 + ur) * DLT + j0 + ujl] = z;
        int pos = (b0 + ur) * 256 + j0 + ujl;
        *(uint32_t*)&g_Hpd[0][0][pos] = 0u;
        *(uint32_t*)&g_Hpd[0][1][pos] = 0u;
    }
    __syncthreads();
    const unsigned base_gen = s_gen0;
    group_barrier(slot, base_gen + 1);     // init + weights + flag reset visible

    const int warp = tid >> 5;
    const int lane = tid & 31;
    const int lg = lane >> 2;
    const int tq = lane & 3;
    const int gate = warp >> 1;
    const int jlb  = (warp & 1) * 16;
    const int rowsel = lane & 15;
    const int koff   = (lane >> 4) * 8;

    const uint32_t boffH = shb + WSH_B + ((warp * 16 + rowsel) * PWS + koff) * 2;
    const uint32_t aoffH = shb + HS_B + (rowsel * PWS + koff) * 2;
    unsigned int* myflag = &g_flagv[(bt * 8 + jt) * 32];
    unsigned int* wflag  = &g_flagv[(bt * 8 + warp) * 32];

    float2 zpre[2][2];
#pragma unroll
    for (int j = 0; j < 2; j++) {
        int col = j0 + jlb + j * 8 + tq * 2;
#pragma unroll
        for (int h = 0; h < 2; h++) {
            int mrow = b0 + lg + h * 8;
            int stash;
            if (gate == 0)      stash = F_OFF + mrow * DLT + col;
            else if (gate == 1) stash = I_OFF + mrow * DLT + col;
            else if (gate == 2) stash = C_OFF + (mrow + BB) * DLT + col;
            else                stash = O_OFF + mrow * DLT + col;
            zpre[j][h] = *(const float2*)&out[stash];
        }
    }

    for (int t = 0; t < TT; t++) {
        // ---- per-warp: wait for producer `warp`, stage its 32-col slice ----
        if (t > 0 && lane == 0) {
            while (ld_acquire_gpu(wflag) < (unsigned)t) { __nanosleep(64); }
        }
        __syncwarp();
        {
            const __nv_bfloat16* hh  = &g_Hpd[t][0][0];
            const __nv_bfloat16* hl_ = &g_Hpd[t][1][0];
#pragma unroll
            for (int c = 0; c < 4; c++) {
                int id = lane + 32 * c;          // 0..127
                int hl = id >> 6;                // 0/1
                int r  = (id >> 2) & 15;
                int cq = id & 3;
                int col = warp * 32 + cq * 8;
                uint32_t sa = shb + HS_B + hl * HL_REL + r * (PWS * 2) + col * 2;
                const __nv_bfloat16* src = (hl ? hl_ : hh) + (b0 + r) * 256 + col;
                cp16cg(sa, src);
            }
            cp_commit();
            cp_wait<0>();
        }
        __syncthreads();

        // ---- mma (R10, unchanged) ----
        float acc[2][4];
#pragma unroll
        for (int j = 0; j < 2; j++)
#pragma unroll
            for (int u = 0; u < 4; u++) acc[j][u] = 0.0f;

#pragma unroll
        for (int k16 = 0; k16 < 256; k16 += 16) {
            uint32_t ah[4], al[4], b4h[4], b4l[4];
            ldsm4(ah,  aoffH + k16 * 2);
            ldsm4(al,  aoffH + HL_REL + k16 * 2);
            ldsm4(b4h, boffH + k16 * 2);
            ldsm4(b4l, boffH + (WSL_B - WSH_B) + k16 * 2);
            uint32_t bh0[2] = { b4h[0], b4h[2] };
            uint32_t bh1[2] = { b4h[1], b4h[3] };
            uint32_t bl0[2] = { b4l[0], b4l[2] };
            uint32_t bl1[2] = { b4l[1], b4l[3] };
            mma16816(acc[0], ah, bh0);
            mma16816(acc[0], ah, bl0);
            mma16816(acc[0], al, bh0);
            mma16816(acc[1], ah, bh1);
            mma16816(acc[1], ah, bl1);
            mma16816(acc[1], al, bh1);
        }

        // ---- epilogue (R10, unchanged) ----
#pragma unroll
        for (int j = 0; j < 2; j++) {
            int jl = jlb + j * 8 + tq * 2;
#pragma unroll
            for (int h = 0; h < 2; h++) {
                int bl_ = lg + h * 8;
                float vx = acc[j][h * 2 + 0] + zpre[j][h].x;
                float vy = acc[j][h * 2 + 1] + zpre[j][h].y;
                float2 r;
                if (gate == 2) { r.x = tanhf(vx); r.y = tanhf(vy); }
                else           { r.x = sigm(vx);  r.y = sigm(vy);  }
                *(float2*)&sg[(gate * 16 + bl_) * 34 + jl] = r;
            }
        }
        __syncthreads();

        // ---- update + publish h_{t+1} (R10 layout) ----
        float2 fv = *(const float2*)&sg[(0 * 16 + ur) * 34 + ujl];
        float2 iv = *(const float2*)&sg[(1 * 16 + ur) * 34 + ujl];
        float2 cv = *(const float2*)&sg[(2 * 16 + ur) * 34 + ujl];
        float2 ov = *(const float2*)&sg[(3 * 16 + ur) * 34 + ujl];
        float2 cold = *(const float2*)&cs[cell];
        float2 cnew, hnew;
        cnew.x = fv.x * cold.x + iv.x * cv.x;
        cnew.y = fv.y * cold.y + iv.y * cv.y;
        hnew.x = ov.x * tanhf(cnew.x);
        hnew.y = ov.y * tanhf(cnew.y);
        *(float2*)&cs[cell] = cnew;

        const int mrow = t * BB + b0 + ur;
        const int jgl  = j0 + ujl;
        *(float2*)&out[H_OFF + (mrow + BB) * DLT + jgl] = hnew;
        {
            uint32_t hi, lo;
            split2(hnew.x, hnew.y, hi, lo);
            int pos = (b0 + ur) * 256 + jgl;
            *(uint32_t*)&g_Hpd[t + 1][0][pos] = hi;
            *(uint32_t*)&g_Hpd[t + 1][1][pos] = lo;
        }
        __syncthreads();

        // ---- release own flag (no central barrier) ----
        if (tid == 0) {
            __threadfence();
            st_release_gpu(myflag, (unsigned)(t + 1));
        }

        // ---- shadowed tail (R10, unchanged) ----
        *(float2*)&out[F_OFF + mrow * DLT + jgl] = fv;
        *(float2*)&out[I_OFF + mrow * DLT + jgl] = iv;
        *(float2*)&out[O_OFF + mrow * DLT + jgl] = ov;
        *(float2*)&out[C_OFF + (mrow + BB) * DLT + jgl] = cnew;

        if (t + 1 < TT) {
#pragma unroll
            for (int j = 0; j < 2; j++) {
                int col = j0 + jlb + j * 8 + tq * 2;
#pragma unroll
                for (int h = 0; h < 2; h++) {
                    int mr2 = (t + 1) * BB + b0 + lg + h * 8;
                    int stash;
                    if (gate == 0)      stash = F_OFF + mr2 * DLT + col;
                    else if (gate == 1) stash = I_OFF + mr2 * DLT + col;
                    else if (gate == 2) stash = C_OFF + (mr2 + BB) * DLT + col;
                    else                stash = O_OFF + mr2 * DLT + col;
                    zpre[j][h] = *(const float2*)&out[stash];
                }
            }
        }
    }
}

// ---------------------------------------------------------------------------
extern "C" void kernel_launch(void* const* d_in, const int* in_sizes, int n_in,
                              void* d_out, int out_size)
{
    const float* X  = (const float*)d_in[0];
    const float* Wf = (const float*)d_in[1];
    const float* bf = (const float*)d_in[2];
    const float* Wi = (const float*)d_in[3];
    const float* bi = (const float*)d_in[4];
    const float* Wc = (const float*)d_in[5];
    const float* bc = (const float*)d_in[6];
    const float* Wo = (const float*)d_in[7];
    const float* bo = (const float*)d_in[8];
    float* out = (float*)d_out;

    cudaFuncSetAttribute(persist_kernel,
                         cudaFuncAttributeMaxDynamicSharedMemorySize, PSMEM);
    cudaFuncSetAttribute(phase1_kernel,
                         cudaFuncAttributeMaxDynamicSharedMemorySize, P1SMEM);

    convX_kernel<<<TT * BB * DIN / 4 / 256, 256>>>(X);
    convW_kernel<<<256, 256>>>(Wf, Wi, Wc, Wo);
    phase1_kernel<<<8192, 256, P1SMEM>>>(bf, bi, bc, bo, out);
    persist_kernel<<<NCTA, 256, PSMEM>>>(Wf, Wi, Wc, Wo, out);
}

// round 16
// speedup vs baseline: 1.5965x; 1.5965x over previous
#include <cuda_runtime.h>
#include <cuda_bf16.h>
#include <math.h>
#include <stdint.h>

#define TT 512
#define BB 256
#define DIN 256
#define DLT 256
#define NCTA 128
#define NGRP 8          // CTAs per barrier group (one b-tile)

// output layout (floats): H[(T+1),B,DL], C[(T+1),B,DL], F[T,B,DL], I[T,B,DL], O[T,B,DL]
#define H_OFF 0
#define C_OFF ((TT + 1) * BB * DLT)
#define F_OFF (2 * (TT + 1) * BB * DLT)
#define I_OFF (F_OFF + TT * BB * DLT)
#define O_OFF (I_OFF + TT * BB * DLT)

// bf16 hi/lo scratch for X and x-side weights
__device__ __nv_bfloat16 g_Xhi[TT * BB * DIN];
__device__ __nv_bfloat16 g_Xlo[TT * BB * DIN];
__device__ __nv_bfloat16 g_Wxhi[4 * DLT * DIN];
__device__ __nv_bfloat16 g_Wxlo[4 * DLT * DIN];

// packed h exchange buffer: [parity][hi/lo][row*256+col], reused every 2 steps
__device__ __nv_bfloat16 g_Hp[2][2][BB * DLT];

// per-group barrier state, 128B-separated
__device__ unsigned int g_cnt2[16 * 32];
__device__ unsigned int g_gen2[16 * 32];

__device__ __forceinline__ float sigm(float x) { return 1.0f / (1.0f + expf(-x)); }

__device__ __forceinline__ unsigned int ld_acquire_gpu(const unsigned int* p)
{
    unsigned int v;
    asm volatile("ld.acquire.gpu.global.u32 %0, [%1];" : "=r"(v) : "l"(p) : "memory");
    return v;
}
__device__ __forceinline__ void red_release_add(unsigned int* p, unsigned int v)
{
    asm volatile("red.release.gpu.global.add.u32 [%0], %1;" :: "l"(p), "r"(v) : "memory");
}
__device__ __forceinline__ void group_barrier(int slot, unsigned target)
{
    __syncthreads();
    if (threadIdx.x == 0) {
        __threadfence();
        if (atomicAdd(&g_cnt2[slot], 1) == NGRP - 1) {
            atomicExch(&g_cnt2[slot], 0);
            red_release_add(&g_gen2[slot], 1);
        } else {
            while (ld_acquire_gpu(&g_gen2[slot]) != target) { __nanosleep(32); }
        }
        __threadfence();
    }
    __syncthreads();
}

__device__ __forceinline__ void split2(float x, float y, uint32_t& hi, uint32_t& lo)
{
    __nv_bfloat16 hx = __float2bfloat16(x);
    __nv_bfloat16 hy = __float2bfloat16(y);
    __nv_bfloat16 lx = __float2bfloat16(x - __bfloat162float(hx));
    __nv_bfloat16 ly = __float2bfloat16(y - __bfloat162float(hy));
    __nv_bfloat162 h2 = __halves2bfloat162(hx, hy);
    __nv_bfloat162 l2 = __halves2bfloat162(lx, ly);
    hi = *(uint32_t*)&h2;
    lo = *(uint32_t*)&l2;
}

__device__ __forceinline__ void mma16816(float* d, const uint32_t* a, const uint32_t* b)
{
    asm volatile(
        "mma.sync.aligned.m16n8k16.row.col.f32.bf16.bf16.f32 "
        "{%0,%1,%2,%3}, {%4,%5,%6,%7}, {%8,%9}, {%0,%1,%2,%3};"
        : "+f"(d[0]), "+f"(d[1]), "+f"(d[2]), "+f"(d[3])
        : "r"(a[0]), "r"(a[1]), "r"(a[2]), "r"(a[3]), "r"(b[0]), "r"(b[1]));
}

__device__ __forceinline__ void ldsm4(uint32_t* r, uint32_t addr)
{
    asm volatile("ldmatrix.sync.aligned.m8n8.x4.shared.b16 {%0,%1,%2,%3}, [%4];"
                 : "=r"(r[0]), "=r"(r[1]), "=r"(r[2]), "=r"(r[3]) : "r"(addr));
}

__device__ __forceinline__ void cp16ca(uint32_t saddr, const void* g)
{
    asm volatile("cp.async.ca.shared.global [%0], [%1], 16;" :: "r"(saddr), "l"(g));
}
__device__ __forceinline__ void cp16cg(uint32_t saddr, const void* g)
{
    asm volatile("cp.async.cg.shared.global [%0], [%1], 16;" :: "r"(saddr), "l"(g));
}
__device__ __forceinline__ void cp_commit() { asm volatile("cp.async.commit_group;"); }
template<int N> __device__ __forceinline__ void cp_wait() { asm volatile("cp.async.wait_group %0;" :: "n"(N)); }

// ---------------------------------------------------------------------------
// converters: fp32 -> bf16 hi/lo, done ONCE  (R10, unchanged)
// ---------------------------------------------------------------------------
__global__ void __launch_bounds__(256) convX_kernel(const float* __restrict__ X)
{
    int idx = blockIdx.x * 256 + threadIdx.x;
    if (idx < TT * BB * DIN / 4) {
        float4 v = *(const float4*)&X[(size_t)idx * 4];
        uint32_t h01, l01, h23, l23;
        split2(v.x, v.y, h01, l01);
        split2(v.z, v.w, h23, l23);
        ((uint2*)g_Xhi)[idx] = make_uint2(h01, h23);
        ((uint2*)g_Xlo)[idx] = make_uint2(l01, l23);
    }
}

__global__ void __launch_bounds__(256) convW_kernel(
    const float* __restrict__ W0, const float* __restrict__ W1,
    const float* __restrict__ W2, const float* __restrict__ W3)
{
    int idx = blockIdx.x * 256 + threadIdx.x;
    int g = idx >> 14;
    int j = (idx >> 6) & 255;
    int q = idx & 63;
    const float* Wg = (g == 0) ? W0 : (g == 1) ? W1 : (g == 2) ? W2 : W3;
    float4 v = *(const float4*)&Wg[(size_t)j * 512 + 256 + q * 4];
    uint32_t h01, l01, h23, l23;
    split2(v.x, v.y, h01, l01);
    split2(v.z, v.w, h23, l23);
    int d2 = g * 16384 + j * 64 + q;
    ((uint2*)g_Wxhi)[d2] = make_uint2(h01, h23);
    ((uint2*)g_Wxlo)[d2] = make_uint2(l01, l23);
}

// ---------------------------------------------------------------------------
// phase 1 (R10, unchanged): cp.async double-buffered + ldmatrix.
// ---------------------------------------------------------------------------
#define P1S 40
#define CHUNK_B 10240
#define BUF_B   (4 * CHUNK_B)
#define P1SMEM  (2 * BUF_B)

__global__ void __launch_bounds__(256) phase1_kernel(
    const float* __restrict__ b0v, const float* __restrict__ b1v,
    const float* __restrict__ b2v, const float* __restrict__ b3v,
    float* __restrict__ out)
{
    extern __shared__ char smem[];
    const uint32_t shb = (uint32_t)__cvta_generic_to_shared(smem);

    const int p  = blockIdx.x;
    const int bx = p & 7;
    const int by = p >> 3;
    const int g  = bx >> 1;
    const int j0 = (bx & 1) * 128;
    const int m0 = by * 128;

    const float* bias = (g == 0) ? b0v : (g == 1) ? b1v : (g == 2) ? b2v : b3v;

    const int tid  = threadIdx.x;
    const int warp = tid >> 5;
    const int lane = tid & 31;
    const int wm = warp >> 1;
    const int wn = warp & 1;
    const int lg = lane >> 2;
    const int tq = lane & 3;
    const int rowsel = lane & 15;
    const int koff   = (lane >> 4) * 8;

    auto stage = [&](int c) {
        int c0 = c * 32;
        uint32_t bufb = shb + (c & 1) * BUF_B;
#pragma unroll
        for (int it = 0; it < 8; it++) {
            int sub  = it >> 1;
            int idx  = tid + (it & 1) * 256;
            int row  = idx >> 2;
            int q    = idx & 3;
            uint32_t sa = bufb + sub * CHUNK_B + (row * P1S + q * 8) * 2;
            const __nv_bfloat16* src;
            if (sub == 0)      src = &g_Xhi[(m0 + row) * 256 + c0 + q * 8];
            else if (sub == 1) src = &g_Xlo[(m0 + row) * 256 + c0 + q * 8];
            else if (sub == 2) src = &g_Wxhi[g * 65536 + (j0 + row) * 256 + c0 + q * 8];
            else               src = &g_Wxlo[g * 65536 + (j0 + row) * 256 + c0 + q * 8];
            cp16ca(sa, src);
        }
        cp_commit();
    };

    float acc[2][8][4];
#pragma unroll
    for (int i = 0; i < 2; i++)
#pragma unroll
        for (int j = 0; j < 8; j++)
#pragma unroll
            for (int u = 0; u < 4; u++) acc[i][j][u] = 0.0f;

    stage(0);

    for (int c = 0; c < 8; c++) {
        if (c + 1 < 8) { stage(c + 1); cp_wait<1>(); }
        else           { cp_wait<0>(); }
        __syncthreads();

        uint32_t bufb = shb + (c & 1) * BUF_B;
        uint32_t aoff = bufb + ((wm * 32 + rowsel) * P1S + koff) * 2;
        uint32_t boff = bufb + 2 * CHUNK_B + ((wn * 64 + rowsel) * P1S + koff) * 2;

#pragma unroll
        for (int kk = 0; kk < 32; kk += 16) {
            uint32_t ah[2][4], al[2][4];
#pragma unroll
            for (int i = 0; i < 2; i++) {
                ldsm4(ah[i], aoff + (i * 16 * P1S + kk) * 2);
                ldsm4(al[i], aoff + CHUNK_B + (i * 16 * P1S + kk) * 2);
            }
#pragma unroll
            for (int jj = 0; jj < 4; jj++) {
                uint32_t b4h[4], b4l[4];
                ldsm4(b4h, boff + (jj * 16 * P1S + kk) * 2);
                ldsm4(b4l, boff + CHUNK_B + (jj * 16 * P1S + kk) * 2);
                uint32_t bh0[2] = { b4h[0], b4h[2] };
                uint32_t bh1[2] = { b4h[1], b4h[3] };
                uint32_t bl0[2] = { b4l[0], b4l[2] };
                uint32_t bl1[2] = { b4l[1], b4l[3] };
#pragma unroll
                for (int i = 0; i < 2; i++) {
                    mma16816(acc[i][jj * 2 + 0], ah[i], bh0);
                    mma16816(acc[i][jj * 2 + 0], ah[i], bl0);
                    mma16816(acc[i][jj * 2 + 0], al[i], bh0);
                    mma16816(acc[i][jj * 2 + 1], ah[i], bh1);
                    mma16816(acc[i][jj * 2 + 1], ah[i], bl1);
                    mma16816(acc[i][jj * 2 + 1], al[i], bh1);
                }
            }
        }
        __syncthreads();
    }

#pragma unroll
    for (int i = 0; i < 2; i++) {
#pragma unroll
        for (int j = 0; j < 8; j++) {
            int col = j0 + wn * 64 + j * 8 + tq * 2;
            float bxv = bias[col], byv = bias[col + 1];
            int row0 = m0 + wm * 32 + i * 16 + lg;
#pragma unroll
            for (int h = 0; h < 2; h++) {
                int m = row0 + h * 8;
                float2 v;
                v.x = acc[i][j][h * 2 + 0] + bxv;
                v.y = acc[i][j][h * 2 + 1] + byv;
                int idx;
                if (g == 0)      idx = F_OFF + m * DLT + col;
                else if (g == 1) idx = I_OFF + m * DLT + col;
                else if (g == 2) idx = C_OFF + (m + BB) * DLT + col;
                else             idx = O_OFF + m * DLT + col;
                *(float2*)&out[idx] = v;
            }
        }
    }
}

// ---------------------------------------------------------------------------
// persist v7 = R10 with per-warp wait: each warp's lane 0 polls the group gen
// and starts staging immediately (one __syncthreads removed from the step
// critical path; the pre-mma __syncthreads still fences the tile).
// Everything else identical to R10.
// ---------------------------------------------------------------------------
#define PWS 264
#define WSH_B 0
#define WSL_B 67584
#define HS_B  135168
#define HL_REL 8448
#define SG_B  152064
#define CS_B  160768
#define PSMEM 162816

__global__ void __launch_bounds__(256) persist_kernel(
    const float* __restrict__ W0, const float* __restrict__ W1,
    const float* __restrict__ W2, const float* __restrict__ W3,
    float* __restrict__ out)
{
    extern __shared__ char smem[];
    __nv_bfloat16* wsH = (__nv_bfloat16*)(smem + WSH_B);
    __nv_bfloat16* wsL = (__nv_bfloat16*)(smem + WSL_B);
    float* sg = (float*)(smem + SG_B);
    float* cs = (float*)(smem + CS_B);
    const uint32_t shb = (uint32_t)__cvta_generic_to_shared(smem);

    const int tid = threadIdx.x;
    const int bt = blockIdx.x >> 3;
    const int jt = blockIdx.x & 7;
    const int b0 = bt * 16;
    const int j0 = jt * 32;
    const int slot = bt * 32;

    __shared__ unsigned s_gen0;
    if (tid == 0) s_gen0 = ld_acquire_gpu(&g_gen2[slot]);

#pragma unroll
    for (int it = 0; it < 32; it++) {
        int idx = tid + it * 256;
        int jc = idx >> 6;
        int kq = idx & 63;
        int gg = jc >> 5;
        int jr = j0 + (jc & 31);
        const float* Wg = (gg == 0) ? W0 : (gg == 1) ? W1 : (gg == 2) ? W2 : W3;
        float4 v = *(const float4*)&Wg[(size_t)jr * 512 + kq * 4];
        uint32_t h01, l01, h23, l23;
        split2(v.x, v.y, h01, l01);
        split2(v.z, v.w, h23, l23);
        int base = jc * PWS + kq * 4;
        *(uint32_t*)&wsH[base]     = h01;
        *(uint32_t*)&wsH[base + 2] = h23;
        *(uint32_t*)&wsL[base]     = l01;
        *(uint32_t*)&wsL[base + 2] = l23;
    }

    const int cell = tid * 2;
    const int ur  = cell >> 5;
    const int ujl = cell & 31;

    {
        float2 z = make_float2(0.0f, 0.0f);
        *(float2*)&cs[cell] = z;
        *(float2*)&out[H_OFF + (b0 + ur) * DLT + j0 + ujl] = z;
        *(float2*)&out[C_OFF + (b0 + ur) * DLT + j0 + ujl] = z;
        int pos = (b0 + ur) * 256 + j0 + ujl;
        *(uint32_t*)&g_Hp[0][0][pos] = 0u;
        *(uint32_t*)&g_Hp[0][1][pos] = 0u;
    }
    __syncthreads();
    const unsigned base_gen = s_gen0;
    group_barrier(slot, base_gen + 1);

    const int warp = tid >> 5;
    const int lane = tid & 31;
    const int lg = lane >> 2;
    const int tq = lane & 3;
    const int gate = warp >> 1;
    const int jlb  = (warp & 1) * 16;
    const int rowsel = lane & 15;
    const int koff   = (lane >> 4) * 8;

    const uint32_t boffH = shb + WSH_B + ((warp * 16 + rowsel) * PWS + koff) * 2;
    const uint32_t aoffH = shb + HS_B + (rowsel * PWS + koff) * 2;

    float2 zpre[2][2];
#pragma unroll
    for (int j = 0; j < 2; j++) {
        int col = j0 + jlb + j * 8 + tq * 2;
#pragma unroll
        for (int h = 0; h < 2; h++) {
            int mrow = b0 + lg + h * 8;
            int stash;
            if (gate == 0)      stash = F_OFF + mrow * DLT + col;
            else if (gate == 1) stash = I_OFF + mrow * DLT + col;
            else if (gate == 2) stash = C_OFF + (mrow + BB) * DLT + col;
            else                stash = O_OFF + mrow * DLT + col;
            zpre[j][h] = *(const float2*)&out[stash];
        }
    }

    for (int t = 0; t < TT; t++) {
        // ---- per-warp wait: h_t published (each warp polls independently) ----
        if (lane == 0) {
            unsigned tgt = base_gen + 1 + (unsigned)t;
            while (ld_acquire_gpu(&g_gen2[slot]) != tgt) { __nanosleep(32); }
        }
        __syncwarp();

        // ---- stage packed h tile via cp.async.cg (L2-only), per-thread share ----
        {
            const int par = t & 1;
#pragma unroll
            for (int it = 0; it < 4; it++) {
                int idx = tid + it * 256;
                int hl  = idx >> 9;
                int r   = (idx >> 5) & 15;
                int q   = idx & 31;
                uint32_t sa = shb + HS_B + hl * HL_REL + r * (PWS * 2) + q * 16;
                cp16cg(sa, &g_Hp[par][hl][(b0 + r) * 256 + q * 8]);
            }
            cp_commit();
            cp_wait<0>();
        }
        __syncthreads();

        float acc[2][4];
#pragma unroll
        for (int j = 0; j < 2; j++)
#pragma unroll
            for (int u = 0; u < 4; u++) acc[j][u] = 0.0f;

#pragma unroll
        for (int k16 = 0; k16 < 256; k16 += 16) {
            uint32_t ah[4], al[4], b4h[4], b4l[4];
            ldsm4(ah,  aoffH + k16 * 2);
            ldsm4(al,  aoffH + HL_REL + k16 * 2);
            ldsm4(b4h, boffH + k16 * 2);
            ldsm4(b4l, boffH + (WSL_B - WSH_B) + k16 * 2);
            uint32_t bh0[2] = { b4h[0], b4h[2] };
            uint32_t bh1[2] = { b4h[1], b4h[3] };
            uint32_t bl0[2] = { b4l[0], b4l[2] };
            uint32_t bl1[2] = { b4l[1], b4l[3] };
            mma16816(acc[0], ah, bh0);
            mma16816(acc[0], ah, bl0);
            mma16816(acc[0], al, bh0);
            mma16816(acc[1], ah, bh1);
            mma16816(acc[1], ah, bl1);
            mma16816(acc[1], al, bh1);
        }

#pragma unroll
        for (int j = 0; j < 2; j++) {
            int jl = jlb + j * 8 + tq * 2;
#pragma unroll
            for (int h = 0; h < 2; h++) {
                int bl_ = lg + h * 8;
                float vx = acc[j][h * 2 + 0] + zpre[j][h].x;
                float vy = acc[j][h * 2 + 1] + zpre[j][h].y;
                float2 r;
                if (gate == 2) { r.x = tanhf(vx); r.y = tanhf(vy); }
                else           { r.x = sigm(vx);  r.y = sigm(vy);  }
                *(float2*)&sg[(gate * 16 + bl_) * 34 + jl] = r;
            }
        }
        __syncthreads();

        float2 fv = *(const float2*)&sg[(0 * 16 + ur) * 34 + ujl];
        float2 iv = *(const float2*)&sg[(1 * 16 + ur) * 34 + ujl];
        float2 cv = *(const float2*)&sg[(2 * 16 + ur) * 34 + ujl];
        float2 ov = *(const float2*)&sg[(3 * 16 + ur) * 34 + ujl];
        float2 cold = *(const float2*)&cs[cell];
        float2 cnew, hnew;
        cnew.x = fv.x * cold.x + iv.x * cv.x;
        cnew.y = fv.y * cold.y + iv.y * cv.y;
        hnew.x = ov.x * tanhf(cnew.x);
        hnew.y = ov.y * tanhf(cnew.y);
        *(float2*)&cs[cell] = cnew;

        const int mrow = t * BB + b0 + ur;
        const int jgl  = j0 + ujl;
        *(float2*)&out[H_OFF + (mrow + BB) * DLT + jgl] = hnew;
        {
            uint32_t hi, lo;
            split2(hnew.x, hnew.y, hi, lo);
            int pos = (b0 + ur) * 256 + jgl;
            *(uint32_t*)&g_Hp[(t + 1) & 1][0][pos] = hi;
            *(uint32_t*)&g_Hp[(t + 1) & 1][1][pos] = lo;
        }
        __syncthreads();

        if (tid == 0) {
            __threadfence();
            if (atomicAdd(&g_cnt2[slot], 1) == NGRP - 1) {
                atomicExch(&g_cnt2[slot], 0);
                red_release_add(&g_gen2[slot], 1);
            }
        }

        *(float2*)&out[F_OFF + mrow * DLT + jgl] = fv;
        *(float2*)&out[I_OFF + mrow * DLT + jgl] = iv;
        *(float2*)&out[O_OFF + mrow * DLT + jgl] = ov;
        *(float2*)&out[C_OFF + (mrow + BB) * DLT + jgl] = cnew;

        if (t + 1 < TT) {
#pragma unroll
            for (int j = 0; j < 2; j++) {
                int col = j0 + jlb + j * 8 + tq * 2;
#pragma unroll
                for (int h = 0; h < 2; h++) {
                    int mr2 = (t + 1) * BB + b0 + lg + h * 8;
                    int stash;
                    if (gate == 0)      stash = F_OFF + mr2 * DLT + col;
                    else if (gate == 1) stash = I_OFF + mr2 * DLT + col;
                    else if (gate == 2) stash = C_OFF + (mr2 + BB) * DLT + col;
                    else                stash = O_OFF + mr2 * DLT + col;
                    zpre[j][h] = *(const float2*)&out[stash];
                }
            }
        }
    }
}

// ---------------------------------------------------------------------------
extern "C" void kernel_launch(void* const* d_in, const int* in_sizes, int n_in,
                              void* d_out, int out_size)
{
    const float* X  = (const float*)d_in[0];
    const float* Wf = (const float*)d_in[1];
    const float* bf = (const float*)d_in[2];
    const float* Wi = (const float*)d_in[3];
    const float* bi = (const float*)d_in[4];
    const float* Wc = (const float*)d_in[5];
    const float* bc = (const float*)d_in[6];
    const float* Wo = (const float*)d_in[7];
    const float* bo = (const float*)d_in[8];
    float* out = (float*)d_out;

    cudaFuncSetAttribute(persist_kernel,
                         cudaFuncAttributeMaxDynamicSharedMemorySize, PSMEM);
    cudaFuncSetAttribute(phase1_kernel,
                         cudaFuncAttributeMaxDynamicSharedMemorySize, P1SMEM);

    convX_kernel<<<TT * BB * DIN / 4 / 256, 256>>>(X);
    convW_kernel<<<256, 256>>>(Wf, Wi, Wc, Wo);
    phase1_kernel<<<8192, 256, P1SMEM>>>(bf, bi, bc, bo, out);
    persist_kernel<<<NCTA, 256, PSMEM>>>(Wf, Wi, Wc, Wo, out);
}